// round 5
// baseline (speedup 1.0000x reference)
#include <cuda_runtime.h>
#include <cstdint>

// Problem constants
#define N_V   50000
#define R_    5
#define A_    8
#define RA    40
#define C_    64
#define KX    2560            // RA * C
#define KTOT  2624            // KX + C (center fold appended)
#define NCOL  512             // O * T
#define KT_N  82              // KTOT / 32
#define KT64  41              // KTOT / 64
#define MB_N  391             // ceil(50048 / 128)

// Scratch (static device arrays — no cudaMalloc allowed)
// A in MMA-fragment layout: per (row-tile mb of 128, k-chunk kt of 32): 4096 floats.
__device__ float g_Afrag[(size_t)MB_N * KT_N * 4096];   // ~513 MB
// B in MMA-fragment layout (kk-contiguous): per (col-tile nb of 128, k-chunk kt): 4096 floats.
__device__ float g_Bfrag[(size_t)4 * KT_N * 4096];      // 5.4 MB
__device__ float g_biasExt[NCOL];

__device__ __forceinline__ float tf32r(float x) {
    uint32_t u;
    asm("cvt.rna.tf32.f32 %0, %1;" : "=r"(u) : "f"(x));
    return __uint_as_float(u);
}

__device__ __forceinline__ uint32_t smem_u32(const void* p) {
    uint32_t a;
    asm("{ .reg .u64 t; cvta.to.shared.u64 t, %1; cvt.u32.u64 %0, t; }" : "=r"(a) : "l"(p));
    return a;
}

// ---------------------------------------------------------------------------
// K0: fold interpolation prior + rotation + center weights into B-fragments.
// New layout within a (nb, kt) 16KB chunk (kk-steps adjacent for LDS.128):
//   idx = ((NT*32 + gn*4 + t4) * 4 + kk) * 2 + r
// ---------------------------------------------------------------------------
__device__ __forceinline__ size_t bfrag_addr(int k, int j) {
    int kt = k >> 5, kl = k & 31;
    int kk = kl >> 3, wi = kl & 7, t4 = wi & 3, r = wi >> 2;
    int nb = j >> 7, nl = j & 127;
    int NT = nl >> 3, gn = nl & 7;
    return ((size_t)(nb * KT_N + kt)) * 4096 +
           (size_t)(((NT * 32 + gn * 4 + t4) * 4 + kk) * 2 + r);
}

__global__ void build_B_kernel(const float* __restrict__ nw,
                               const float* __restrict__ cw,
                               const float* __restrict__ bias,
                               const float* __restrict__ coeff)
{
    int j = blockIdx.x;            // 0..511
    int o = j >> 6;
    int t = j & 63;
    int c = threadIdx.x;           // 64 threads

    __shared__ float s_coeff[R_ * A_ * RA];
    for (int i = c; i < R_ * A_ * RA; i += 64) s_coeff[i] = coeff[i];
    __syncthreads();

    float wv[R_][A_];
    #pragma unroll
    for (int r = 0; r < R_; r++)
        #pragma unroll
        for (int a = 0; a < A_; a++)
            wv[r][a] = nw[(((size_t)t * R_ + r) * A_ + ((a + o) & 7)) * C_ + c];

    for (int m = 0; m < RA; m++) {
        float acc = 0.f;
        #pragma unroll
        for (int r = 0; r < R_; r++)
            #pragma unroll
            for (int a = 0; a < A_; a++)
                acc += s_coeff[(r * A_ + a) * RA + m] * wv[r][a];
        g_Bfrag[bfrag_addr(m * C_ + c, j)] = tf32r(acc);
    }
    g_Bfrag[bfrag_addr(KX + c, j)] = tf32r(cw[t * C_ + c]);
    if (c == 0) g_biasExt[j] = bias[t];
}

// ---------------------------------------------------------------------------
// K1: barycentric gather + interpolation, written directly as A-fragments.
// One block per vertex PAIR (n, n+8). (A layout unchanged.)
// ---------------------------------------------------------------------------
__global__ __launch_bounds__(256)
void build_X_kernel(const float* __restrict__ ms,
                    const float* __restrict__ bary)
{
    int bp = blockIdx.x;
    int mb = bp >> 6;
    int q  = bp & 63;
    int MT = q >> 3;
    int gl = q & 7;
    int n0 = mb * 128 + MT * 16 + gl;

    __shared__ float s_row[2][KTOT];
    __shared__ float sb[240];
    int tid = threadIdx.x;

    #pragma unroll
    for (int v = 0; v < 2; v++) {
        int n = n0 + 8 * v;
        if (n < N_V) {
            if (tid < 240) sb[tid] = bary[(size_t)n * 240 + tid];
            __syncthreads();
            int g4 = tid >> 6;
            int c  = tid & 63;
            #pragma unroll
            for (int it = 0; it < 10; it++) {
                int m  = it * 4 + g4;
                int i0 = (int)sb[m * 6 + 0]; float w0 = sb[m * 6 + 1];
                int i1 = (int)sb[m * 6 + 2]; float w1 = sb[m * 6 + 3];
                int i2 = (int)sb[m * 6 + 4]; float w2 = sb[m * 6 + 5];
                s_row[v][m * C_ + c] = w0 * ms[(size_t)i0 * C_ + c]
                                     + w1 * ms[(size_t)i1 * C_ + c]
                                     + w2 * ms[(size_t)i2 * C_ + c];
            }
            if (g4 == 0) s_row[v][KX + c] = ms[(size_t)n * C_ + c];
        } else {
            for (int i = tid; i < KTOT; i += 256) s_row[v][i] = 0.f;
        }
        __syncthreads();
    }

    for (int w = tid; w < KT_N * 16; w += 256) {
        int kt = w >> 4;
        int kk = (w >> 2) & 3;
        int t4 = w & 3;
        int k  = kt * 32 + kk * 8 + t4;
        float4 val = make_float4(tf32r(s_row[0][k]), tf32r(s_row[0][k + 4]),
                                 tf32r(s_row[1][k]), tf32r(s_row[1][k + 4]));
        ((float4*)(g_Afrag + ((size_t)mb * KT_N + kt) * 4096))
            [(MT * 4 + kk) * 32 + gl * 4 + t4] = val;
    }
}

// ---------------------------------------------------------------------------
// K2: tf32 mma.sync GEMM + bias + relu.
// BM=128, BN=256, BK=64. 256 threads = 8 warps (2m x 4n), warp tile 64x64.
// 2-stage cp.async pipeline, 96KB per stage.
// ---------------------------------------------------------------------------
__device__ __forceinline__ void mma_tf32(float* c, float a0, float a1, float a2, float a3,
                                         float b0, float b1)
{
    asm volatile(
        "mma.sync.aligned.m16n8k8.row.col.f32.tf32.tf32.f32 "
        "{%0,%1,%2,%3}, {%4,%5,%6,%7}, {%8,%9}, {%0,%1,%2,%3};\n"
        : "+f"(c[0]), "+f"(c[1]), "+f"(c[2]), "+f"(c[3])
        : "r"(__float_as_uint(a0)), "r"(__float_as_uint(a1)),
          "r"(__float_as_uint(a2)), "r"(__float_as_uint(a3)),
          "r"(__float_as_uint(b0)), "r"(__float_as_uint(b1)));
}

__device__ __forceinline__ void cp16(uint32_t s, const void* g) {
    asm volatile("cp.async.cg.shared.global [%0], [%1], 16;" :: "r"(s), "l"(g));
}
__device__ __forceinline__ float4 lds128(uint32_t a) {
    float4 v;
    asm volatile("ld.shared.v4.f32 {%0,%1,%2,%3}, [%4];"
                 : "=f"(v.x), "=f"(v.y), "=f"(v.z), "=f"(v.w) : "r"(a));
    return v;
}

#define STAGE_BYTES 98304      // 32KB A + 64KB B
#define SMEM_TOTAL  (2 * STAGE_BYTES)   // 192KB

__global__ __launch_bounds__(256)
void gemm_relu_kernel(float* __restrict__ out)
{
    extern __shared__ float smemf[];
    uint32_t sbase = smem_u32(smemf);

    int tid  = threadIdx.x;
    int warp = tid >> 5;
    int ln   = tid & 31;
    int wm   = warp >> 2;          // 0..1  (m half, 64 rows)
    int wn   = warp & 3;           // 0..3  (n quarter, 64 cols)
    int mb   = blockIdx.y;
    int bx   = blockIdx.x;         // 0..1  (n half of 256)

    const float* Ag  = g_Afrag + (size_t)mb * KT_N * 4096;
    const float* Bg0 = g_Bfrag + (size_t)(bx * 2 + 0) * KT_N * 4096;
    const float* Bg1 = g_Bfrag + (size_t)(bx * 2 + 1) * KT_N * 4096;

    // one stage = 64 K: A 2 chunks (8192 fl), B: nb0 2 chunks, nb1 2 chunks
    auto issue = [&](int s) {
        uint32_t dst = sbase + (uint32_t)(s & 1) * STAGE_BYTES;
        const float* As = Ag + (size_t)s * 8192;
        #pragma unroll
        for (int i = 0; i < 8; i++)
            cp16(dst + (tid + i * 256) * 16, As + (tid + i * 256) * 4);
        const float* Bs0 = Bg0 + (size_t)s * 8192;
        const float* Bs1 = Bg1 + (size_t)s * 8192;
        #pragma unroll
        for (int i = 0; i < 8; i++)
            cp16(dst + 32768 + (tid + i * 256) * 16, Bs0 + (tid + i * 256) * 4);
        #pragma unroll
        for (int i = 0; i < 8; i++)
            cp16(dst + 65536 + (tid + i * 256) * 16, Bs1 + (tid + i * 256) * 4);
    };

    issue(0);
    asm volatile("cp.async.commit_group;" ::: "memory");

    float acc[4][8][4];
    #pragma unroll
    for (int mt = 0; mt < 4; mt++)
        #pragma unroll
        for (int nt = 0; nt < 8; nt++)
            #pragma unroll
            for (int i = 0; i < 4; i++) acc[mt][nt][i] = 0.f;

    for (int kt = 0; kt < KT64; kt++) {
        if (kt < KT64 - 1) {
            issue(kt + 1);
            asm volatile("cp.async.commit_group;" ::: "memory");
            asm volatile("cp.async.wait_group 1;" ::: "memory");
        } else {
            asm volatile("cp.async.wait_group 0;" ::: "memory");
        }
        __syncthreads();

        uint32_t bufA = sbase + (uint32_t)(kt & 1) * STAGE_BYTES;
        uint32_t bufB = bufA + 32768 + (uint32_t)(wn >> 1) * 32768;

        #pragma unroll
        for (int kkp = 0; kkp < 4; kkp++) {
            uint32_t chunk = (uint32_t)(kkp >> 1) * 16384;
            int kkl = (kkp * 2) & 3;       // 0 or 2 within chunk
            float4 af[2][4];
            float4 bf[8];
            #pragma unroll
            for (int mt = 0; mt < 4; mt++) {
                uint32_t a = bufA + chunk + ((((wm * 4 + mt) * 4 + kkl) * 32 + ln) * 16);
                af[0][mt] = lds128(a);
                af[1][mt] = lds128(a + 512);      // kkl+1: +32 floats
            }
            #pragma unroll
            for (int nt = 0; nt < 8; nt++) {
                int NT = (wn & 1) * 8 + nt;
                // v4 covers (kkl: r0,r1), (kkl+1: r0,r1)
                bf[nt] = lds128(bufB + chunk + (((NT * 32 + ln) * 4 + kkl) * 8));
            }
            #pragma unroll
            for (int mt = 0; mt < 4; mt++)
                #pragma unroll
                for (int nt = 0; nt < 8; nt++) {
                    // A frag float4 = (a0, a2, a1, a3)
                    mma_tf32(acc[mt][nt], af[0][mt].x, af[0][mt].z, af[0][mt].y, af[0][mt].w,
                             bf[nt].x, bf[nt].y);
                    mma_tf32(acc[mt][nt], af[1][mt].x, af[1][mt].z, af[1][mt].y, af[1][mt].w,
                             bf[nt].z, bf[nt].w);
                }
        }
        if (kt < KT64 - 1) __syncthreads();
    }

    // epilogue: bias + relu
    int g  = ln >> 2;
    int t4 = ln & 3;
    #pragma unroll
    for (int nt = 0; nt < 8; nt++) {
        int col = bx * 256 + wn * 64 + nt * 8 + t4 * 2;
        float b0 = g_biasExt[col];
        float b1 = g_biasExt[col + 1];
        #pragma unroll
        for (int mt = 0; mt < 4; mt++) {
            int row0 = mb * 128 + wm * 64 + mt * 16 + g;
            float v0 = acc[mt][nt][0] + b0;
            float v1 = acc[mt][nt][1] + b1;
            float v2 = acc[mt][nt][2] + b0;
            float v3 = acc[mt][nt][3] + b1;
            v0 = v0 > 0.f ? v0 : 0.f;
            v1 = v1 > 0.f ? v1 : 0.f;
            v2 = v2 > 0.f ? v2 : 0.f;
            v3 = v3 > 0.f ? v3 : 0.f;
            if (row0 < N_V)
                *(float2*)(out + (size_t)row0 * NCOL + col) = make_float2(v0, v1);
            if (row0 + 8 < N_V)
                *(float2*)(out + (size_t)(row0 + 8) * NCOL + col) = make_float2(v2, v3);
        }
    }
}

// ---------------------------------------------------------------------------
// Launch
// Inputs: mesh_signal, bary_coordinates, neighbor_weights, center_weights,
//         bias, interp_coeff
// ---------------------------------------------------------------------------
extern "C" void kernel_launch(void* const* d_in, const int* in_sizes, int n_in,
                              void* d_out, int out_size)
{
    const float* ms    = (const float*)d_in[0];
    const float* bary  = (const float*)d_in[1];
    const float* nw    = (const float*)d_in[2];
    const float* cw    = (const float*)d_in[3];
    const float* bias  = (const float*)d_in[4];
    const float* coeff = (const float*)d_in[5];
    float* out = (float*)d_out;

    cudaFuncSetAttribute(gemm_relu_kernel,
                         cudaFuncAttributeMaxDynamicSharedMemorySize, SMEM_TOTAL);

    build_B_kernel<<<NCOL, 64>>>(nw, cw, bias, coeff);
    build_X_kernel<<<MB_N * 64, 256>>>(ms, bary);

    dim3 grid(2, MB_N);
    gemm_relu_kernel<<<grid, 256, SMEM_TOTAL>>>(out);
}